// round 1
// baseline (speedup 1.0000x reference)
#include <cuda_runtime.h>
#include <cstdint>

#define NMAX 50000
#define GNUM 512
#define HID 64
#define LAY 5
#define HL 320   // HID*LAY
#define BN_EPS 1e-5f

// ---------------- static scratch (no allocations allowed) ----------------
__device__ float g_agg [(size_t)NMAX * HID];   // per-layer aggregation
__device__ float g_agg0[(size_t)NMAX];         // layer-0 scalar aggregation
__device__ float g_z   [(size_t)NMAX * HID];   // post-GEMM1 pre-BN
__device__ float g_v   [(size_t)NMAX * HID];   // post-GEMM2 pre-BN
__device__ float g_outs[(size_t)NMAX * HL];    // JK concat buffer [N,320], h_l at col l*64
__device__ float g_stats[4 * HID];             // sum1, sq1, sum2, sq2
__device__ float g_coef [4 * HID];             // a1, b1, a2, b2 (BN scale/shift)
__device__ int   g_starts[GNUM + 1];
__device__ int   g_is64_e;
__device__ int   g_is64_b;

__device__ __forceinline__ long ldidx(const void* p, long i, int is64) {
    return is64 ? (long)((const long long*)p)[i] : (long)((const int*)p)[i];
}

// ---------------- dtype detection (int64 vs int32 indices) ----------------
__global__ void detect_kernel(const void* ei, const void* batch, int ncount) {
    __shared__ int flag;
    const int* p = (const int*)ei;
    if (threadIdx.x == 0) flag = 0;
    __syncthreads();
    // if data is int64 little-endian with values < 2^31, every odd int32 is 0
    for (int i = threadIdx.x; i < 4096; i += blockDim.x)
        if (p[2 * i + 1] != 0) atomicOr(&flag, 1);
    __syncthreads();
    if (threadIdx.x == 0) { g_is64_e = (flag == 0); flag = 0; }
    __syncthreads();
    const int* q = (const int*)batch;
    int half = ncount / 2;
    for (int i = threadIdx.x; i < 2048; i += blockDim.x) {
        int pos = half - 1 - i;
        if (pos >= 0 && q[2 * pos + 1] != 0) atomicOr(&flag, 1);
    }
    __syncthreads();
    if (threadIdx.x == 0) g_is64_b = (flag == 0);
}

// ---------------- zeroing ----------------
__global__ void zero_l0_kernel(int n) {
    int i = blockIdx.x * blockDim.x + threadIdx.x;
    if (i < n)   g_agg0[i]  = 0.f;
    if (i < 256) g_stats[i] = 0.f;
}
__global__ void zero_l_kernel(int n64) {
    int i = blockIdx.x * blockDim.x + threadIdx.x;
    if (i < n64) g_agg[i]   = 0.f;
    if (i < 256) g_stats[i] = 0.f;
}

// ---------------- aggregation ----------------
__global__ void agg0_kernel(const void* __restrict__ ei, const float* __restrict__ x, int E) {
    int e = blockIdx.x * blockDim.x + threadIdx.x;
    if (e >= E) return;
    int is64 = g_is64_e;
    long src = ldidx(ei, e, is64);
    long dst = ldidx(ei, (long)E + e, is64);
    atomicAdd(&g_agg0[dst], x[src]);
}

__global__ void agg_kernel(const void* __restrict__ ei, int E, int prevcol) {
    long gid = (long)blockIdx.x * blockDim.x + threadIdx.x;
    if (gid >= (long)E * 16) return;
    int e    = (int)(gid >> 4);
    int part = (int)(gid & 15);
    int is64 = g_is64_e;
    long src = ldidx(ei, e, is64);
    long dst = ldidx(ei, (long)E + e, is64);
    const float4 v = *(const float4*)(g_outs + (size_t)src * HL + prevcol + part * 4);
    float* dp = g_agg + (size_t)dst * HID + part * 4;
    unsigned long long gp = (unsigned long long)__cvta_generic_to_global(dp);
    asm volatile("red.global.add.v4.f32 [%0], {%1,%2,%3,%4};"
                 :: "l"(gp), "f"(v.x), "f"(v.y), "f"(v.z), "f"(v.w) : "memory");
}

// ---------------- layer 0 GEMM1 (C_IN=1 -> outer product) + stats ----------------
__global__ __launch_bounds__(256) void l0_gemm_kernel(
    const float* __restrict__ x, const float* __restrict__ w,
    const float* __restrict__ bias, int n)
{
    int t = threadIdx.x;
    int c = t & 63;
    int g = t >> 6;
    int r0 = blockIdx.x * 256 + g * 64;
    float wc = w[c], bc = bias[c];
    float s = 0.f, q = 0.f;
    int rend = min(r0 + 64, n);
    for (int i = r0; i < rend; i++) {
        float zv = (x[i] + g_agg0[i]) * wc + bc;
        g_z[(size_t)i * HID + c] = zv;
        s += zv; q += zv * zv;
    }
    atomicAdd(&g_stats[c], s);
    atomicAdd(&g_stats[64 + c], q);
}

// ---------------- generic fused 64x64 GEMMs + stats ----------------
// GEMM1: in = h(prevcol of g_outs, ld=320) + g_agg, out = g_z, stats[0..127]
__global__ __launch_bounds__(256) void gemm1_kernel(
    int prevcol, const float* __restrict__ w, const float* __restrict__ bias, int n)
{
    __shared__ float s_in[64][65];
    __shared__ float s_w[64][64];
    int t = threadIdx.x;
    int r0 = blockIdx.x * 64;
    for (int idx = t; idx < 4096; idx += 256)
        s_w[idx >> 6][idx & 63] = w[idx];
    for (int idx = t; idx < 4096; idx += 256) {
        int r = idx >> 6, k = idx & 63;
        int gr = r0 + r;
        float val = 0.f;
        if (gr < n)
            val = g_outs[(size_t)gr * HL + prevcol + k] + g_agg[(size_t)gr * HID + k];
        s_in[r][k] = val;
    }
    __syncthreads();
    int r = t & 63, cg = t >> 6, c0 = cg * 16;
    float acc[16];
    #pragma unroll
    for (int j = 0; j < 16; j++) acc[j] = bias[c0 + j];
    #pragma unroll
    for (int k = 0; k < 64; k++) {
        float a = s_in[r][k];
        const float4* wrow = (const float4*)&s_w[k][c0];
        #pragma unroll
        for (int m = 0; m < 4; m++) {
            float4 wv = wrow[m];
            acc[4*m+0] = fmaf(a, wv.x, acc[4*m+0]);
            acc[4*m+1] = fmaf(a, wv.y, acc[4*m+1]);
            acc[4*m+2] = fmaf(a, wv.z, acc[4*m+2]);
            acc[4*m+3] = fmaf(a, wv.w, acc[4*m+3]);
        }
    }
    int gr = r0 + r;
    bool valid = gr < n;
    if (valid) {
        float4* op = (float4*)&g_z[(size_t)gr * HID + c0];
        #pragma unroll
        for (int m = 0; m < 4; m++)
            op[m] = make_float4(acc[4*m], acc[4*m+1], acc[4*m+2], acc[4*m+3]);
    }
    #pragma unroll
    for (int j = 0; j < 16; j++) {
        float s = valid ? acc[j] : 0.f;
        float q = s * s;
        #pragma unroll
        for (int o = 16; o > 0; o >>= 1) {
            s += __shfl_down_sync(0xFFFFFFFFu, s, o);
            q += __shfl_down_sync(0xFFFFFFFFu, q, o);
        }
        if ((t & 31) == 0) {
            atomicAdd(&g_stats[c0 + j], s);
            atomicAdd(&g_stats[64 + c0 + j], q);
        }
    }
}

// GEMM2: in = relu(BN(g_z)) via coef[0..127], out = g_v, stats[128..255]
__global__ __launch_bounds__(256) void gemm2_kernel(
    const float* __restrict__ w, const float* __restrict__ bias, int n)
{
    __shared__ float s_in[64][65];
    __shared__ float s_w[64][64];
    __shared__ float s_a[64], s_b[64];
    int t = threadIdx.x;
    if (t < 64) { s_a[t] = g_coef[t]; s_b[t] = g_coef[64 + t]; }
    __syncthreads();
    int r0 = blockIdx.x * 64;
    for (int idx = t; idx < 4096; idx += 256)
        s_w[idx >> 6][idx & 63] = w[idx];
    for (int idx = t; idx < 4096; idx += 256) {
        int r = idx >> 6, k = idx & 63;
        int gr = r0 + r;
        float val = 0.f;
        if (gr < n)
            val = fmaxf(fmaf(g_z[(size_t)gr * HID + k], s_a[k], s_b[k]), 0.f);
        s_in[r][k] = val;
    }
    __syncthreads();
    int r = t & 63, cg = t >> 6, c0 = cg * 16;
    float acc[16];
    #pragma unroll
    for (int j = 0; j < 16; j++) acc[j] = bias[c0 + j];
    #pragma unroll
    for (int k = 0; k < 64; k++) {
        float a = s_in[r][k];
        const float4* wrow = (const float4*)&s_w[k][c0];
        #pragma unroll
        for (int m = 0; m < 4; m++) {
            float4 wv = wrow[m];
            acc[4*m+0] = fmaf(a, wv.x, acc[4*m+0]);
            acc[4*m+1] = fmaf(a, wv.y, acc[4*m+1]);
            acc[4*m+2] = fmaf(a, wv.z, acc[4*m+2]);
            acc[4*m+3] = fmaf(a, wv.w, acc[4*m+3]);
        }
    }
    int gr = r0 + r;
    bool valid = gr < n;
    if (valid) {
        float4* op = (float4*)&g_v[(size_t)gr * HID + c0];
        #pragma unroll
        for (int m = 0; m < 4; m++)
            op[m] = make_float4(acc[4*m], acc[4*m+1], acc[4*m+2], acc[4*m+3]);
    }
    #pragma unroll
    for (int j = 0; j < 16; j++) {
        float s = valid ? acc[j] : 0.f;
        float q = s * s;
        #pragma unroll
        for (int o = 16; o > 0; o >>= 1) {
            s += __shfl_down_sync(0xFFFFFFFFu, s, o);
            q += __shfl_down_sync(0xFFFFFFFFu, q, o);
        }
        if ((t & 31) == 0) {
            atomicAdd(&g_stats[128 + c0 + j], s);
            atomicAdd(&g_stats[192 + c0 + j], q);
        }
    }
}

// ---------------- BN coefficient computation ----------------
__global__ void coef_kernel(const float* __restrict__ gamma, const float* __restrict__ beta,
                            int statoff, int coefoff, float invN)
{
    int c = threadIdx.x;  // 64 threads
    float mean = g_stats[statoff + c] * invN;
    float var  = g_stats[statoff + 64 + c] * invN - mean * mean;
    float inv  = rsqrtf(var + BN_EPS);
    float a    = gamma[c] * inv;
    g_coef[coefoff + c]      = a;
    g_coef[coefoff + 64 + c] = beta[c] - mean * a;
}

// ---------------- BN+ReLU writeback into JK buffer ----------------
__global__ void bnout_kernel(int n, int lcol) {
    int idx = blockIdx.x * blockDim.x + threadIdx.x;
    if (idx >= n * 16) return;
    int row = idx >> 4, q = idx & 15;
    int c0 = q * 4;
    float4 v = ((const float4*)g_v)[idx];
    float a0 = g_coef[128 + c0 + 0], b0 = g_coef[192 + c0 + 0];
    float a1 = g_coef[128 + c0 + 1], b1 = g_coef[192 + c0 + 1];
    float a2 = g_coef[128 + c0 + 2], b2 = g_coef[192 + c0 + 2];
    float a3 = g_coef[128 + c0 + 3], b3 = g_coef[192 + c0 + 3];
    float4 r;
    r.x = fmaxf(fmaf(v.x, a0, b0), 0.f);
    r.y = fmaxf(fmaf(v.y, a1, b1), 0.f);
    r.z = fmaxf(fmaf(v.z, a2, b2), 0.f);
    r.w = fmaxf(fmaf(v.w, a3, b3), 0.f);
    *(float4*)(g_outs + (size_t)row * HL + lcol + c0) = r;
}

// ---------------- graph segment starts (batch sorted) ----------------
__global__ void starts_kernel(const void* __restrict__ batch, int n) {
    int i = blockIdx.x * blockDim.x + threadIdx.x;
    if (i >= n) return;
    int is64 = g_is64_b;
    int bi = (int)ldidx(batch, i, is64);
    int bp = (i == 0) ? -1 : (int)ldidx(batch, i - 1, is64);
    for (int g = bp + 1; g <= bi; g++) g_starts[g] = i;
    if (i == n - 1)
        for (int g = bi + 1; g <= GNUM; g++) g_starts[g] = n;
}

// ---------------- pooling + classifier (fused) ----------------
__global__ void pool_kernel(const float* __restrict__ x, const float* __restrict__ lin_w,
                            const float* __restrict__ lin_b, float* __restrict__ out)
{
    int g = blockIdx.x;
    int s = g_starts[g], e = g_starts[g + 1];
    __shared__ float sd[HL + 1];
    for (int c = threadIdx.x; c < HL + 1; c += blockDim.x) {
        float acc = 0.f;
        if (c == 0) {
            for (int r = s; r < e; r++) acc += x[r];
        } else {
            for (int r = s; r < e; r++) acc += g_outs[(size_t)r * HL + (c - 1)];
        }
        sd[c] = acc;
    }
    __syncthreads();
    if (threadIdx.x < 2) {
        float acc = lin_b[threadIdx.x];
        for (int c = 0; c < HL + 1; c++)
            acc = fmaf(sd[c], lin_w[c * 2 + threadIdx.x], acc);
        out[g * 2 + threadIdx.x] = acc;
    }
}

// ---------------- launch ----------------
extern "C" void kernel_launch(void* const* d_in, const int* in_sizes, int n_in,
                              void* d_out, int out_size)
{
    const float* x      = (const float*)d_in[0];
    const void*  ei     = d_in[1];
    const void*  batch  = d_in[2];
    const float* w1_0   = (const float*)d_in[3];
    const float* w1_rest= (const float*)d_in[4];
    const float* b1     = (const float*)d_in[5];
    const float* gm     = (const float*)d_in[6];
    const float* bm     = (const float*)d_in[7];
    const float* w2     = (const float*)d_in[8];
    const float* b2     = (const float*)d_in[9];
    const float* go     = (const float*)d_in[10];
    const float* bo     = (const float*)d_in[11];
    const float* lin_w  = (const float*)d_in[12];
    const float* lin_b  = (const float*)d_in[13];
    float* out = (float*)d_out;

    int N = in_sizes[0];           // C_IN = 1
    int E = in_sizes[1] / 2;
    float invN = 1.f / (float)N;

    detect_kernel<<<1, 256>>>(ei, batch, in_sizes[2]);

    int gemmGrid = (N + 63) / 64;
    int bnGrid   = (N * 16 + 255) / 256;

    // ---- layer 0 ----
    zero_l0_kernel<<<(N + 255) / 256, 256>>>(N);
    agg0_kernel<<<(E + 255) / 256, 256>>>(ei, x, E);
    l0_gemm_kernel<<<(N + 255) / 256, 256>>>(x, w1_0, b1, N);
    coef_kernel<<<1, 64>>>(gm, bm, 0, 0, invN);
    gemm2_kernel<<<gemmGrid, 256>>>(w2, b2, N);
    coef_kernel<<<1, 64>>>(go, bo, 128, 128, invN);
    bnout_kernel<<<bnGrid, 256>>>(N, 0);

    // ---- layers 1..4 ----
    for (int l = 1; l < LAY; l++) {
        zero_l_kernel<<<(N * HID + 255) / 256, 256>>>(N * HID);
        long aggThreads = (long)E * 16;
        agg_kernel<<<(unsigned)((aggThreads + 255) / 256), 256>>>(ei, E, (l - 1) * HID);
        gemm1_kernel<<<gemmGrid, 256>>>((l - 1) * HID, w1_rest + (size_t)(l - 1) * HID * HID,
                                        b1 + l * HID, N);
        coef_kernel<<<1, 64>>>(gm + l * HID, bm + l * HID, 0, 0, invN);
        gemm2_kernel<<<gemmGrid, 256>>>(w2 + (size_t)l * HID * HID, b2 + l * HID, N);
        coef_kernel<<<1, 64>>>(go + l * HID, bo + l * HID, 128, 128, invN);
        bnout_kernel<<<bnGrid, 256>>>(N, l * HID);
    }

    // ---- pooling + classifier ----
    starts_kernel<<<(N + 255) / 256, 256>>>(batch, N);
    pool_kernel<<<GNUM, 256>>>(x, lin_w, lin_b, out);
}

// round 2
// speedup vs baseline: 1.1155x; 1.1155x over previous
#include <cuda_runtime.h>
#include <cstdint>

#define NMAX 50000
#define EMAX 800000
#define GNUM 512
#define HID 64
#define LAY 5
#define HL 320   // HID*LAY
#define BN_EPS 1e-5f

// ---------------- static scratch ----------------
__device__ float g_agg [(size_t)NMAX * HID];
__device__ float g_agg0[NMAX];
__device__ float g_z   [(size_t)NMAX * HID];
__device__ float g_v   [(size_t)NMAX * HID];
__device__ float g_outs[(size_t)NMAX * HL];    // JK concat [N,320]
__device__ float g_stats[LAY * 256];           // per layer: sum1,sq1,sum2,sq2
__device__ float g_coef [4 * HID];             // a1,b1,a2,b2 (transient per layer)
__device__ int   g_starts[GNUM + 1];
__device__ int   g_is64_e, g_is64_b;
// CSR
__device__ int   g_deg[NMAX];
__device__ int   g_rowptr[NMAX + 1];
__device__ int   g_cur[NMAX];
__device__ int   g_part[256];
__device__ int   g_partscan[256];
__device__ int   g_csrc[EMAX];

__device__ __forceinline__ long ldidx(const void* p, long i, int is64) {
    return is64 ? (long)((const long long*)p)[i] : (long)((const int*)p)[i];
}

// ---------------- dtype detection ----------------
__global__ void detect_kernel(const void* ei, const void* batch, int ncount) {
    __shared__ int flag;
    const int* p = (const int*)ei;
    if (threadIdx.x == 0) flag = 0;
    __syncthreads();
    for (int i = threadIdx.x; i < 4096; i += blockDim.x)
        if (p[2 * i + 1] != 0) atomicOr(&flag, 1);
    __syncthreads();
    if (threadIdx.x == 0) { g_is64_e = (flag == 0); flag = 0; }
    __syncthreads();
    const int* q = (const int*)batch;
    int half = ncount / 2;
    for (int i = threadIdx.x; i < 2048; i += blockDim.x) {
        int pos = half - 1 - i;
        if (pos >= 0 && q[2 * pos + 1] != 0) atomicOr(&flag, 1);
    }
    __syncthreads();
    if (threadIdx.x == 0) g_is64_b = (flag == 0);
}

// ---------------- CSR build ----------------
__global__ void zero_deg_stats_kernel(int n) {
    int i = blockIdx.x * blockDim.x + threadIdx.x;
    if (i < n) g_deg[i] = 0;
    if (i < LAY * 256) g_stats[i] = 0.f;
}

__global__ void hist_kernel(const void* __restrict__ ei, int E) {
    int e = blockIdx.x * blockDim.x + threadIdx.x;
    if (e >= E) return;
    int is64 = g_is64_e;
    int dst = (int)ldidx(ei, (long)E + e, is64);
    atomicAdd(&g_deg[dst], 1);
}

__global__ void scan1_kernel(int n) {
    __shared__ int sh[256];
    int i = blockIdx.x * 256 + threadIdx.x;
    int v = (i < n) ? g_deg[i] : 0;
    sh[threadIdx.x] = v;
    __syncthreads();
    for (int off = 128; off > 0; off >>= 1) {
        if (threadIdx.x < off) sh[threadIdx.x] += sh[threadIdx.x + off];
        __syncthreads();
    }
    if (threadIdx.x == 0) g_part[blockIdx.x] = sh[0];
}

__global__ void scan2_kernel(int nblocks) {
    __shared__ int sh[256];
    int t = threadIdx.x;
    int v = (t < nblocks) ? g_part[t] : 0;
    sh[t] = v;
    __syncthreads();
    for (int off = 1; off < 256; off <<= 1) {
        int x = (t >= off) ? sh[t - off] : 0;
        __syncthreads();
        sh[t] += x;
        __syncthreads();
    }
    if (t < nblocks) g_partscan[t] = sh[t] - v;   // exclusive
}

__global__ void scan3_kernel(int n, int E) {
    __shared__ int sh[256];
    int t = threadIdx.x;
    int i = blockIdx.x * 256 + t;
    int v = (i < n) ? g_deg[i] : 0;
    sh[t] = v;
    __syncthreads();
    for (int off = 1; off < 256; off <<= 1) {
        int x = (t >= off) ? sh[t - off] : 0;
        __syncthreads();
        sh[t] += x;
        __syncthreads();
    }
    if (i < n) {
        int rp = g_partscan[blockIdx.x] + sh[t] - v;  // exclusive
        g_rowptr[i] = rp;
        g_cur[i] = rp;
        if (i == n - 1) g_rowptr[n] = E;
    }
}

__global__ void fill_kernel(const void* __restrict__ ei, int E) {
    int e = blockIdx.x * blockDim.x + threadIdx.x;
    if (e >= E) return;
    int is64 = g_is64_e;
    int src = (int)ldidx(ei, e, is64);
    int dst = (int)ldidx(ei, (long)E + e, is64);
    int pos = atomicAdd(&g_cur[dst], 1);
    g_csrc[pos] = src;
}

// ---------------- aggregation (gather, no atomics) ----------------
__global__ void agg0_gather_kernel(const float* __restrict__ x, int n) {
    int i = blockIdx.x * blockDim.x + threadIdx.x;
    if (i >= n) return;
    int beg = g_rowptr[i], end = g_rowptr[i + 1];
    float acc = 0.f;
    for (int j = beg; j < end; j++) acc += x[g_csrc[j]];
    g_agg0[i] = acc;
}

// one warp per node; lanes split even/odd neighbors, float4 channels
__global__ __launch_bounds__(256) void agg_gather_kernel(int prevcol, int n) {
    int node = blockIdx.x * 8 + (threadIdx.x >> 5);
    if (node >= n) return;
    int lane = threadIdx.x & 31;
    int half = lane >> 4;          // 0 or 1
    int c4   = lane & 15;          // channel/4
    int beg = g_rowptr[node], end = g_rowptr[node + 1];
    float4 acc = make_float4(0.f, 0.f, 0.f, 0.f);
    for (int j = beg + half; j < end; j += 2) {
        int src = g_csrc[j];
        float4 v = *(const float4*)(g_outs + (size_t)src * HL + prevcol + c4 * 4);
        acc.x += v.x; acc.y += v.y; acc.z += v.z; acc.w += v.w;
    }
    acc.x += __shfl_xor_sync(0xFFFFFFFFu, acc.x, 16);
    acc.y += __shfl_xor_sync(0xFFFFFFFFu, acc.y, 16);
    acc.z += __shfl_xor_sync(0xFFFFFFFFu, acc.z, 16);
    acc.w += __shfl_xor_sync(0xFFFFFFFFu, acc.w, 16);
    if (half == 0)
        *(float4*)(g_agg + (size_t)node * HID + c4 * 4) = acc;
}

// ---------------- layer 0 GEMM1 (C_IN=1 outer product) + stats ----------------
__global__ __launch_bounds__(256) void l0_gemm_kernel(
    const float* __restrict__ x, const float* __restrict__ w,
    const float* __restrict__ bias, int n, int statoff)
{
    int t = threadIdx.x;
    int c = t & 63;
    int g = t >> 6;
    int r0 = blockIdx.x * 256 + g * 64;
    float wc = w[c], bc = bias[c];
    float s = 0.f, q = 0.f;
    int rend = min(r0 + 64, n);
    for (int i = r0; i < rend; i++) {
        float zv = (x[i] + g_agg0[i]) * wc + bc;
        g_z[(size_t)i * HID + c] = zv;
        s += zv; q += zv * zv;
    }
    atomicAdd(&g_stats[statoff + c], s);
    atomicAdd(&g_stats[statoff + 64 + c], q);
}

// ---------------- fused 64x64 GEMMs + stats ----------------
__global__ __launch_bounds__(256) void gemm1_kernel(
    int prevcol, const float* __restrict__ w, const float* __restrict__ bias,
    int n, int statoff)
{
    __shared__ float s_in[64][65];
    __shared__ float s_w[64][64];
    int t = threadIdx.x;
    int r0 = blockIdx.x * 64;
    for (int idx = t; idx < 4096; idx += 256)
        s_w[idx >> 6][idx & 63] = w[idx];
    for (int idx = t; idx < 4096; idx += 256) {
        int r = idx >> 6, k = idx & 63;
        int gr = r0 + r;
        float val = 0.f;
        if (gr < n)
            val = g_outs[(size_t)gr * HL + prevcol + k] + g_agg[(size_t)gr * HID + k];
        s_in[r][k] = val;
    }
    __syncthreads();
    int r = t & 63, cg = t >> 6, c0 = cg * 16;
    float acc[16];
    #pragma unroll
    for (int j = 0; j < 16; j++) acc[j] = bias[c0 + j];
    #pragma unroll
    for (int k = 0; k < 64; k++) {
        float a = s_in[r][k];
        const float4* wrow = (const float4*)&s_w[k][c0];
        #pragma unroll
        for (int m = 0; m < 4; m++) {
            float4 wv = wrow[m];
            acc[4*m+0] = fmaf(a, wv.x, acc[4*m+0]);
            acc[4*m+1] = fmaf(a, wv.y, acc[4*m+1]);
            acc[4*m+2] = fmaf(a, wv.z, acc[4*m+2]);
            acc[4*m+3] = fmaf(a, wv.w, acc[4*m+3]);
        }
    }
    int gr = r0 + r;
    bool valid = gr < n;
    if (valid) {
        float4* op = (float4*)&g_z[(size_t)gr * HID + c0];
        #pragma unroll
        for (int m = 0; m < 4; m++)
            op[m] = make_float4(acc[4*m], acc[4*m+1], acc[4*m+2], acc[4*m+3]);
    }
    #pragma unroll
    for (int j = 0; j < 16; j++) {
        float s = valid ? acc[j] : 0.f;
        float q = s * s;
        #pragma unroll
        for (int o = 16; o > 0; o >>= 1) {
            s += __shfl_down_sync(0xFFFFFFFFu, s, o);
            q += __shfl_down_sync(0xFFFFFFFFu, q, o);
        }
        if ((t & 31) == 0) {
            atomicAdd(&g_stats[statoff + c0 + j], s);
            atomicAdd(&g_stats[statoff + 64 + c0 + j], q);
        }
    }
}

__global__ __launch_bounds__(256) void gemm2_kernel(
    const float* __restrict__ w, const float* __restrict__ bias,
    int n, int statoff)
{
    __shared__ float s_in[64][65];
    __shared__ float s_w[64][64];
    __shared__ float s_a[64], s_b[64];
    int t = threadIdx.x;
    if (t < 64) { s_a[t] = g_coef[t]; s_b[t] = g_coef[64 + t]; }
    __syncthreads();
    int r0 = blockIdx.x * 64;
    for (int idx = t; idx < 4096; idx += 256)
        s_w[idx >> 6][idx & 63] = w[idx];
    for (int idx = t; idx < 4096; idx += 256) {
        int r = idx >> 6, k = idx & 63;
        int gr = r0 + r;
        float val = 0.f;
        if (gr < n)
            val = fmaxf(fmaf(g_z[(size_t)gr * HID + k], s_a[k], s_b[k]), 0.f);
        s_in[r][k] = val;
    }
    __syncthreads();
    int r = t & 63, cg = t >> 6, c0 = cg * 16;
    float acc[16];
    #pragma unroll
    for (int j = 0; j < 16; j++) acc[j] = bias[c0 + j];
    #pragma unroll
    for (int k = 0; k < 64; k++) {
        float a = s_in[r][k];
        const float4* wrow = (const float4*)&s_w[k][c0];
        #pragma unroll
        for (int m = 0; m < 4; m++) {
            float4 wv = wrow[m];
            acc[4*m+0] = fmaf(a, wv.x, acc[4*m+0]);
            acc[4*m+1] = fmaf(a, wv.y, acc[4*m+1]);
            acc[4*m+2] = fmaf(a, wv.z, acc[4*m+2]);
            acc[4*m+3] = fmaf(a, wv.w, acc[4*m+3]);
        }
    }
    int gr = r0 + r;
    bool valid = gr < n;
    if (valid) {
        float4* op = (float4*)&g_v[(size_t)gr * HID + c0];
        #pragma unroll
        for (int m = 0; m < 4; m++)
            op[m] = make_float4(acc[4*m], acc[4*m+1], acc[4*m+2], acc[4*m+3]);
    }
    #pragma unroll
    for (int j = 0; j < 16; j++) {
        float s = valid ? acc[j] : 0.f;
        float q = s * s;
        #pragma unroll
        for (int o = 16; o > 0; o >>= 1) {
            s += __shfl_down_sync(0xFFFFFFFFu, s, o);
            q += __shfl_down_sync(0xFFFFFFFFu, q, o);
        }
        if ((t & 31) == 0) {
            atomicAdd(&g_stats[statoff + c0 + j], s);
            atomicAdd(&g_stats[statoff + 64 + c0 + j], q);
        }
    }
}

// ---------------- BN coefficients ----------------
__global__ void coef_kernel(const float* __restrict__ gamma, const float* __restrict__ beta,
                            int statoff, int coefoff, float invN)
{
    int c = threadIdx.x;  // 64
    float mean = g_stats[statoff + c] * invN;
    float var  = g_stats[statoff + 64 + c] * invN - mean * mean;
    float inv  = rsqrtf(var + BN_EPS);
    float a    = gamma[c] * inv;
    g_coef[coefoff + c]      = a;
    g_coef[coefoff + 64 + c] = beta[c] - mean * a;
}

// ---------------- BN+ReLU writeback into JK buffer ----------------
__global__ void bnout_kernel(int n, int lcol) {
    int idx = blockIdx.x * blockDim.x + threadIdx.x;
    if (idx >= n * 16) return;
    int row = idx >> 4, q = idx & 15;
    int c0 = q * 4;
    float4 v = ((const float4*)g_v)[idx];
    float a0 = g_coef[128 + c0 + 0], b0 = g_coef[192 + c0 + 0];
    float a1 = g_coef[128 + c0 + 1], b1 = g_coef[192 + c0 + 1];
    float a2 = g_coef[128 + c0 + 2], b2 = g_coef[192 + c0 + 2];
    float a3 = g_coef[128 + c0 + 3], b3 = g_coef[192 + c0 + 3];
    float4 r;
    r.x = fmaxf(fmaf(v.x, a0, b0), 0.f);
    r.y = fmaxf(fmaf(v.y, a1, b1), 0.f);
    r.z = fmaxf(fmaf(v.z, a2, b2), 0.f);
    r.w = fmaxf(fmaf(v.w, a3, b3), 0.f);
    *(float4*)(g_outs + (size_t)row * HL + lcol + c0) = r;
}

// ---------------- pooling ----------------
__global__ void starts_kernel(const void* __restrict__ batch, int n) {
    int i = blockIdx.x * blockDim.x + threadIdx.x;
    if (i >= n) return;
    int is64 = g_is64_b;
    int bi = (int)ldidx(batch, i, is64);
    int bp = (i == 0) ? -1 : (int)ldidx(batch, i - 1, is64);
    for (int g = bp + 1; g <= bi; g++) g_starts[g] = i;
    if (i == n - 1)
        for (int g = bi + 1; g <= GNUM; g++) g_starts[g] = n;
}

__global__ void pool_kernel(const float* __restrict__ x, const float* __restrict__ lin_w,
                            const float* __restrict__ lin_b, float* __restrict__ out)
{
    int g = blockIdx.x;
    int s = g_starts[g], e = g_starts[g + 1];
    __shared__ float sd[HL + 1];
    for (int c = threadIdx.x; c < HL + 1; c += blockDim.x) {
        float acc = 0.f;
        if (c == 0) {
            for (int r = s; r < e; r++) acc += x[r];
        } else {
            for (int r = s; r < e; r++) acc += g_outs[(size_t)r * HL + (c - 1)];
        }
        sd[c] = acc;
    }
    __syncthreads();
    if (threadIdx.x < 2) {
        float acc = lin_b[threadIdx.x];
        for (int c = 0; c < HL + 1; c++)
            acc = fmaf(sd[c], lin_w[c * 2 + threadIdx.x], acc);
        out[g * 2 + threadIdx.x] = acc;
    }
}

// ---------------- launch ----------------
extern "C" void kernel_launch(void* const* d_in, const int* in_sizes, int n_in,
                              void* d_out, int out_size)
{
    const float* x      = (const float*)d_in[0];
    const void*  ei     = d_in[1];
    const void*  batch  = d_in[2];
    const float* w1_0   = (const float*)d_in[3];
    const float* w1_rest= (const float*)d_in[4];
    const float* b1     = (const float*)d_in[5];
    const float* gm     = (const float*)d_in[6];
    const float* bm     = (const float*)d_in[7];
    const float* w2     = (const float*)d_in[8];
    const float* b2     = (const float*)d_in[9];
    const float* go     = (const float*)d_in[10];
    const float* bo     = (const float*)d_in[11];
    const float* lin_w  = (const float*)d_in[12];
    const float* lin_b  = (const float*)d_in[13];
    float* out = (float*)d_out;

    int N = in_sizes[0];
    int E = in_sizes[1] / 2;
    float invN = 1.f / (float)N;

    int nb256 = (N + 255) / 256;
    int eb256 = (E + 255) / 256;
    int gemmGrid = (N + 63) / 64;
    int bnGrid   = (N * 16 + 255) / 256;

    detect_kernel<<<1, 256>>>(ei, batch, in_sizes[2]);

    // ---- CSR build + stat zeroing ----
    zero_deg_stats_kernel<<<nb256, 256>>>(N);
    hist_kernel<<<eb256, 256>>>(ei, E);
    scan1_kernel<<<nb256, 256>>>(N);
    scan2_kernel<<<1, 256>>>(nb256);
    scan3_kernel<<<nb256, 256>>>(N, E);
    fill_kernel<<<eb256, 256>>>(ei, E);

    // ---- layer 0 ----
    agg0_gather_kernel<<<nb256, 256>>>(x, N);
    l0_gemm_kernel<<<nb256, 256>>>(x, w1_0, b1, N, 0);
    coef_kernel<<<1, 64>>>(gm, bm, 0, 0, invN);
    gemm2_kernel<<<gemmGrid, 256>>>(w2, b2, N, 128);
    coef_kernel<<<1, 64>>>(go, bo, 128, 128, invN);
    bnout_kernel<<<bnGrid, 256>>>(N, 0);

    // ---- layers 1..4 ----
    for (int l = 1; l < LAY; l++) {
        int so = l * 256;
        agg_gather_kernel<<<(N + 7) / 8, 256>>>((l - 1) * HID, N);
        gemm1_kernel<<<gemmGrid, 256>>>((l - 1) * HID,
                                        w1_rest + (size_t)(l - 1) * HID * HID,
                                        b1 + l * HID, N, so);
        coef_kernel<<<1, 64>>>(gm + l * HID, bm + l * HID, so, 0, invN);
        gemm2_kernel<<<gemmGrid, 256>>>(w2 + (size_t)l * HID * HID, b2 + l * HID, N, so + 128);
        coef_kernel<<<1, 64>>>(go + l * HID, bo + l * HID, so + 128, 128, invN);
        bnout_kernel<<<bnGrid, 256>>>(N, l * HID);
    }

    // ---- pooling + classifier ----
    starts_kernel<<<nb256, 256>>>(batch, N);
    pool_kernel<<<GNUM, 256>>>(x, lin_w, lin_b, out);
}